// round 13
// baseline (speedup 1.0000x reference)
#include <cuda_runtime.h>
#include <cuda_fp16.h>
#include <cstdint>
#include <cstddef>

// Problem constants
#define NEXP 8
#define TOPK 2
#define DIM 1024
#define DFF 4096
#define NTOK 16384          // B*S
#define CAP  16384          // per-expert capacity
#define RTOT (NTOK * TOPK)  // 32768 expert-rows
#define PADR 128            // row padding for tile overrun

// ---------------- scratch (device globals; DEVICE-CODE REFERENCES ONLY) ------
// RULE (rounds 2-5): never pass these symbols as host-side kernel args — the
// host shadow is ATS-readable on GB300 and silently reads zeros.
__device__ int    g_cnt[NEXP];
__device__ int    g_off[NEXP];
__device__ int    g_tok[NEXP * CAP];
__device__ float  g_wtl[NEXP * CAP];
__device__ __half g_Xh[(size_t)(RTOT + PADR) * DIM];   // gathered x, fp16
__device__ __half g_Hh[(size_t)(RTOT + PADR) * DFF];   // hidden scratch, fp16
__device__ __half g_W1h[(size_t)NEXP * DIM * DFF];     // W1^T: [DFF][DIM], fp16
__device__ __half g_W2h[(size_t)NEXP * DFF * DIM];     // W2^T: [DIM][DFF], fp16

// ---------------- helpers ----------------------------------------------------
__device__ __forceinline__ void mma_f16(float c[4], const unsigned a[4], const unsigned b[2]) {
    asm volatile(
        "mma.sync.aligned.m16n8k16.row.col.f32.f16.f16.f32 "
        "{%0,%1,%2,%3}, {%4,%5,%6,%7}, {%8,%9}, {%0,%1,%2,%3};\n"
        : "+f"(c[0]), "+f"(c[1]), "+f"(c[2]), "+f"(c[3])
        : "r"(a[0]), "r"(a[1]), "r"(a[2]), "r"(a[3]), "r"(b[0]), "r"(b[1]));
}
__device__ __forceinline__ void ldsm_x4(unsigned& r0, unsigned& r1, unsigned& r2,
                                        unsigned& r3, uint32_t addr) {
    asm volatile("ldmatrix.sync.aligned.m8n8.x4.shared.b16 {%0,%1,%2,%3}, [%4];"
                 : "=r"(r0), "=r"(r1), "=r"(r2), "=r"(r3) : "r"(addr));
}
__device__ __forceinline__ void cpasync16(uint32_t d, const void* s) {
    asm volatile("cp.async.cg.shared.global [%0], [%1], 16;" :: "r"(d), "l"(s));
}
__device__ __forceinline__ void cp_commit() { asm volatile("cp.async.commit_group;"); }
template <int N>
__device__ __forceinline__ void cp_wait() {
    asm volatile("cp.async.wait_group %0;" :: "n"(N));
}

// ---------------- kernel 0-2: routing ----------------------------------------
__global__ void zero_kernel() {
    if (threadIdx.x < NEXP) g_cnt[threadIdx.x] = 0;
}

__global__ void zero_out_kernel(float4* __restrict__ out) {
    out[blockIdx.x * 256 + threadIdx.x] = make_float4(0.f, 0.f, 0.f, 0.f);
}

__global__ void route_kernel(const float* __restrict__ x, const float* __restrict__ gw) {
    __shared__ float s_gw[NEXP * DIM];
    int tid = threadIdx.x;
    for (int i = tid; i < NEXP * DIM; i += blockDim.x) s_gw[i] = gw[i];
    __syncthreads();

    int warp = tid >> 5, lane = tid & 31;
    int t = blockIdx.x * (blockDim.x >> 5) + warp;
    if (t >= NTOK) return;

    const float* xr = x + (size_t)t * DIM;
    float xv[32];
#pragma unroll
    for (int i = 0; i < 32; i++) xv[i] = xr[i * 32 + lane];

    float logit[NEXP];
#pragma unroll
    for (int e = 0; e < NEXP; e++) {
        float acc = 0.f;
#pragma unroll
        for (int i = 0; i < 32; i++) acc += xv[i] * s_gw[e * DIM + i * 32 + lane];
#pragma unroll
        for (int o = 16; o; o >>= 1) acc += __shfl_xor_sync(0xffffffffu, acc, o);
        logit[e] = acc;
    }

    if (lane == 0) {
        int i0 = 0;
#pragma unroll
        for (int e = 1; e < NEXP; e++) if (logit[e] > logit[i0]) i0 = e;
        int i1 = (i0 == 0) ? 1 : 0;
#pragma unroll
        for (int e = 0; e < NEXP; e++) {
            if (e == i0 || e == i1) continue;
            if (logit[e] > logit[i1]) i1 = e;
        }
        float ee = __expf(logit[i1] - logit[i0]);
        float inv = 1.f / (1.f + ee);
        int p0 = atomicAdd(&g_cnt[i0], 1);
        g_tok[i0 * CAP + p0] = t;  g_wtl[i0 * CAP + p0] = inv;
        int p1 = atomicAdd(&g_cnt[i1], 1);
        g_tok[i1 * CAP + p1] = t;  g_wtl[i1 * CAP + p1] = ee * inv;
    }
}

__global__ void prefix_kernel() {
    if (threadIdx.x == 0) {
        int s = 0;
#pragma unroll
        for (int e = 0; e < NEXP; e++) { g_off[e] = s; s += g_cnt[e]; }
    }
}

// ---------------- kernel 3: weight prep: fp16 convert + transpose to [N][K] ---
template <int WHICH>   // 0: W1 (K=DIM, N=DFF) -> g_W1h;  1: W2 (K=DFF, N=DIM) -> g_W2h
__global__ void wprep_kernel(const float* __restrict__ src) {
    constexpr int K = WHICH ? DFF : DIM;
    constexpr int N = WHICH ? DIM : DFF;
    __shared__ float t[32][33];
    __half* dall = WHICH ? g_W2h : g_W1h;          // device-side symbol
    int e = blockIdx.z;
    const float* s = src + (size_t)e * K * N;
    __half* d = dall + (size_t)e * K * N;
    int nb = blockIdx.x * 32, kb = blockIdx.y * 32;
    int tx = threadIdx.x, ty = threadIdx.y;        // block (32, 8)
#pragma unroll
    for (int j = 0; j < 4; j++)
        t[ty + j * 8][tx] = s[(size_t)(kb + ty + j * 8) * N + nb + tx];
    __syncthreads();
#pragma unroll
    for (int j = 0; j < 4; j++)
        d[(size_t)(nb + ty + j * 8) * K + kb + tx] = __float2half_rn(t[tx][ty + j * 8]);
}

// ---------------- kernel 4: gather x -> fp16 ----------------------------------
__global__ void gather_kernel(const float* __restrict__ x) {
    int e = blockIdx.y, m = blockIdx.x;
    if (m >= g_cnt[e]) return;
    int tok = g_tok[e * CAP + m];
    int row = g_off[e] + m;
    const float4* src = (const float4*)(x + (size_t)tok * DIM);
    int t = threadIdx.x;                           // 128 threads, 8 halves each
    float4 a = src[2 * t], b = src[2 * t + 1];
    union { uint4 u; __half2 h[4]; } pk;
    pk.h[0] = __floats2half2_rn(a.x, a.y);
    pk.h[1] = __floats2half2_rn(a.z, a.w);
    pk.h[2] = __floats2half2_rn(b.x, b.y);
    pk.h[3] = __floats2half2_rn(b.z, b.w);
    *(uint4*)(g_Xh + (size_t)row * DIM + t * 8) = pk.u;
}

// ---------------- kernels 5/6: cp.async + ldmatrix fp16 grouped GEMM ----------
// A [m][k] and B = W^T [n][k], fp16 K-major rows, RS=BK+8 halves (row bank
// shift 4 -> LDSM conflict-free). mma m16n8k16 fp32 accumulate.
// Fragments double-buffered across ks to hide LDSM latency under HMMA.
// MODE 0: Hh = fp16(silu(Xh @ W1 + b1))   (KDIM=DIM,  NDIM=DFF)
// MODE 1: out[tok] += (Hh @ W2 + b2) * wt (KDIM=DFF,  NDIM=DIM)  [atomicAdd]
template <int KDIM, int NDIM, int MODE>
__global__ void __launch_bounds__(256, 1) ffn_gemm(const float* __restrict__ ball,
                                                   float* __restrict__ outp) {
    constexpr int BM = 128, BN = 256, BK = 64, STAGES = 3;
    constexpr int RS = BK + 8;                  // halves: 72 (144B rows)
    constexpr int SAH = BM * RS;                // 9216 halves
    constexpr int SBH = BN * RS;                // 18432 halves
    constexpr int SSH = SAH + SBH;              // 27648 halves = 55296 B / stage
    constexpr int KT = KDIM / BK;
    constexpr int NN = NDIM / BN;
    constexpr int GM = 16;                      // raster group (L2 reuse)

    extern __shared__ __half sm[];

    const __half* Ain = (MODE == 0) ? g_Xh : g_Hh;     // device symbols
    const __half* Wt  = (MODE == 0) ? g_W1h : g_W2h;

    int e = blockIdx.z;
    int cnt = g_cnt[e];
    int per = GM * NN;
    int grp = blockIdx.x / per;
    int rem = blockIdx.x - grp * per;
    int mb = grp * GM + (rem % GM);
    int nb = rem / GM;
    int m0 = mb * BM;
    if (m0 >= cnt) return;
    int n0 = nb * BN;
    int off = g_off[e];

    const __half* Abase = Ain + (size_t)(off + m0) * KDIM;
    const __half* Bbase = Wt + (size_t)e * KDIM * NDIM + (size_t)n0 * KDIM;
    const float* bias = ball + (size_t)e * NDIM;

    int tid = threadIdx.x;
    int warp = tid >> 5, lane = tid & 31;
    int wm = warp & 1, wn = warp >> 1;           // 2 (M) x 4 (N); warp tile 64x64
    int group = lane >> 2, tig = lane & 3;

    uint32_t sbase = (uint32_t)__cvta_generic_to_shared(sm);

    // staging maps (16B = 8-half chunks): A 1024 chunks, B 2048 chunks
    const __half* a_src[4];
    uint32_t a_dst[4];
#pragma unroll
    for (int i = 0; i < 4; i++) {
        int c = tid + 256 * i;                   // 128 rows x 8 chunks
        int r = c >> 3, s = c & 7;
        a_src[i] = Abase + (size_t)r * KDIM + s * 8;
        a_dst[i] = (uint32_t)((r * RS + s * 8) * 2);
    }
    const __half* b_src[8];
    uint32_t b_dst[8];
#pragma unroll
    for (int i = 0; i < 8; i++) {
        int c = tid + 256 * i;                   // 256 rows x 8 chunks
        int n = c >> 3, s = c & 7;
        b_src[i] = Bbase + (size_t)n * KDIM + s * 8;
        b_dst[i] = (uint32_t)((SAH + n * RS + s * 8) * 2);
    }

    auto issue = [&](int kt, int stage) {
        uint32_t sb = sbase + (uint32_t)(stage * SSH * 2);
#pragma unroll
        for (int i = 0; i < 4; i++)
            cpasync16(sb + a_dst[i], a_src[i] + (size_t)kt * BK);
#pragma unroll
        for (int i = 0; i < 8; i++)
            cpasync16(sb + b_dst[i], b_src[i] + (size_t)kt * BK);
    };

    // ldmatrix per-thread components (textbook fp16 recipe)
    int lrow = lane & 15;                        // row within 16-block
    int lchk = (lane >> 4) * 8;                  // k offset in halves: 0 / 8

    float acc[4][8][4];
#pragma unroll
    for (int mi = 0; mi < 4; mi++)
#pragma unroll
        for (int ni = 0; ni < 8; ni++)
#pragma unroll
            for (int r = 0; r < 4; r++) acc[mi][ni][r] = 0.f;

    // double-buffered fragment registers
    unsigned af[2][4][4], bf[2][8][2];

    issue(0, 0); cp_commit();
    issue(1, 1); cp_commit();

    for (int kt = 0; kt < KT; kt++) {
        cp_wait<1>();
        __syncthreads();                         // stage kt resident
        if (kt + 2 < KT) issue(kt + 2, (kt + 2) % STAGES);
        cp_commit();

        uint32_t sA = sbase + (uint32_t)((kt % STAGES) * SSH * 2);
        uint32_t sB = sA + (uint32_t)(SAH * 2);

        auto ldfrag = [&](int ks, int buf) {
            int kk = ks * 16;
#pragma unroll
            for (int mi = 0; mi < 4; mi++) {
                uint32_t addr = sA + (uint32_t)(((wm * 64 + mi * 16 + lrow) * RS
                                                + kk + lchk) * 2);
                ldsm_x4(af[buf][mi][0], af[buf][mi][1],
                        af[buf][mi][2], af[buf][mi][3], addr);
            }
#pragma unroll
            for (int nj = 0; nj < 4; nj++) {
                uint32_t addr = sB + (uint32_t)(((wn * 64 + nj * 16 + lrow) * RS
                                                + kk + lchk) * 2);
                unsigned r0, r1, r2, r3;
                ldsm_x4(r0, r1, r2, r3, addr);
                bf[buf][2 * nj][0]     = r0;  bf[buf][2 * nj][1]     = r2;
                bf[buf][2 * nj + 1][0] = r1;  bf[buf][2 * nj + 1][1] = r3;
            }
        };

        ldfrag(0, 0);
#pragma unroll
        for (int ks = 0; ks < 4; ks++) {         // K=16 per step
            if (ks < 3) ldfrag(ks + 1, (ks + 1) & 1);   // prefetch next frags
            int cb = ks & 1;
#pragma unroll
            for (int mi = 0; mi < 4; mi++)
#pragma unroll
                for (int ni = 0; ni < 8; ni++)
                    mma_f16(acc[mi][ni], af[cb][mi], bf[cb][ni]);
        }
        __syncthreads();
    }

    // epilogue (fp32 math; MODE 0 -> fp16 H, MODE 1 -> atomicAdd to out)
#pragma unroll
    for (int mi = 0; mi < 4; mi++) {
#pragma unroll
        for (int half = 0; half < 2; half++) {
            int m = m0 + wm * 64 + mi * 16 + group + half * 8;
            if (m >= cnt) continue;
            if (MODE == 0) {
                size_t rowbase = (size_t)(off + m) * NDIM;
#pragma unroll
                for (int ni = 0; ni < 8; ni++) {
                    int c = n0 + wn * 64 + ni * 8 + tig * 2;
                    float v0 = acc[mi][ni][half * 2 + 0] + bias[c];
                    float v1 = acc[mi][ni][half * 2 + 1] + bias[c + 1];
                    v0 = v0 / (1.f + __expf(-v0));
                    v1 = v1 / (1.f + __expf(-v1));
                    *(__half2*)(g_Hh + rowbase + c) = __floats2half2_rn(v0, v1);
                }
            } else {
                int tok = g_tok[e * CAP + m];
                float w = g_wtl[e * CAP + m];
                float* orow = outp + (size_t)tok * NDIM;
#pragma unroll
                for (int ni = 0; ni < 8; ni++) {
                    int c = n0 + wn * 64 + ni * 8 + tig * 2;
                    // exactly 2 contributions per element, fp32 add commutative
                    atomicAdd(&orow[c],     (acc[mi][ni][half * 2 + 0] + bias[c]) * w);
                    atomicAdd(&orow[c + 1], (acc[mi][ni][half * 2 + 1] + bias[c + 1]) * w);
                }
            }
        }
    }
}

// ---------------- launch ------------------------------------------------------
extern "C" void kernel_launch(void* const* d_in, const int* in_sizes, int n_in,
                              void* d_out, int out_size) {
    const float* x  = (const float*)d_in[0];
    const float* gw = (const float*)d_in[1];
    const float* W1 = (const float*)d_in[2];
    const float* b1 = (const float*)d_in[3];
    const float* W2 = (const float*)d_in[4];
    const float* b2 = (const float*)d_in[5];
    float* out = (float*)d_out;

    // opt into >48KB dynamic smem (attribute call, not an allocation)
    constexpr int GEMM_SMEM = 3 * (128 * 72 + 256 * 72) * 2;   // 165,888 B
    cudaFuncSetAttribute(ffn_gemm<DIM, DFF, 0>,
                         cudaFuncAttributeMaxDynamicSharedMemorySize, GEMM_SMEM);
    cudaFuncSetAttribute(ffn_gemm<DFF, DIM, 1>,
                         cudaFuncAttributeMaxDynamicSharedMemorySize, GEMM_SMEM);

    zero_kernel<<<1, 32>>>();
    zero_out_kernel<<<(NTOK * (DIM / 4)) / 256, 256>>>((float4*)out);
    route_kernel<<<NTOK / 8, 256>>>(x, gw);
    prefix_kernel<<<1, 32>>>();

    // weight prep: fp16 convert + transpose to [N][K]
    wprep_kernel<0><<<dim3(DFF / 32, DIM / 32, NEXP), dim3(32, 8)>>>(W1);
    wprep_kernel<1><<<dim3(DIM / 32, DFF / 32, NEXP), dim3(32, 8)>>>(W2);
    gather_kernel<<<dim3(CAP, NEXP), 128>>>(x);

    // GEMM1: (CAP/128) * (DFF/256) = 128 * 16 blocks, z = experts
    ffn_gemm<DIM, DFF, 0><<<dim3((CAP / 128) * (DFF / 256), 1, NEXP), 256, GEMM_SMEM>>>(b1, nullptr);
    // GEMM2: accumulates straight into out (two slots per token, commutative)
    ffn_gemm<DFF, DIM, 1><<<dim3((CAP / 128) * (DIM / 256), 1, NEXP), 256, GEMM_SMEM>>>(b2, out);
}

// round 14
// speedup vs baseline: 1.0497x; 1.0497x over previous
#include <cuda_runtime.h>
#include <cuda_fp16.h>
#include <cstdint>
#include <cstddef>

// Problem constants
#define NEXP 8
#define TOPK 2
#define DIM 1024
#define DFF 4096
#define NTOK 16384          // B*S
#define CAP  16384          // per-expert capacity
#define RTOT (NTOK * TOPK)  // 32768 expert-rows
#define PADR 128            // row padding for tile overrun

// ---------------- scratch (device globals; DEVICE-CODE REFERENCES ONLY) ------
// RULE (rounds 2-5): never pass these symbols as host-side kernel args — the
// host shadow is ATS-readable on GB300 and silently reads zeros.
__device__ int    g_cnt[NEXP];
__device__ int    g_off[NEXP];
__device__ int    g_tok[NEXP * CAP];
__device__ float  g_wtl[NEXP * CAP];
__device__ __half g_Xh[(size_t)(RTOT + PADR) * DIM];   // gathered x, fp16
__device__ __half g_Hh[(size_t)(RTOT + PADR) * DFF];   // hidden scratch, fp16
__device__ __half g_W1h[(size_t)NEXP * DIM * DFF];     // W1^T: [DFF][DIM], fp16
__device__ __half g_W2h[(size_t)NEXP * DFF * DIM];     // W2^T: [DIM][DFF], fp16

// ---------------- helpers ----------------------------------------------------
__device__ __forceinline__ void mma_f16(float c[4], const unsigned a[4], const unsigned b[2]) {
    asm volatile(
        "mma.sync.aligned.m16n8k16.row.col.f32.f16.f16.f32 "
        "{%0,%1,%2,%3}, {%4,%5,%6,%7}, {%8,%9}, {%0,%1,%2,%3};\n"
        : "+f"(c[0]), "+f"(c[1]), "+f"(c[2]), "+f"(c[3])
        : "r"(a[0]), "r"(a[1]), "r"(a[2]), "r"(a[3]), "r"(b[0]), "r"(b[1]));
}
__device__ __forceinline__ void ldsm_x4(unsigned& r0, unsigned& r1, unsigned& r2,
                                        unsigned& r3, uint32_t addr) {
    asm volatile("ldmatrix.sync.aligned.m8n8.x4.shared.b16 {%0,%1,%2,%3}, [%4];"
                 : "=r"(r0), "=r"(r1), "=r"(r2), "=r"(r3) : "r"(addr));
}
__device__ __forceinline__ void cpasync16(uint32_t d, const void* s) {
    asm volatile("cp.async.cg.shared.global [%0], [%1], 16;" :: "r"(d), "l"(s));
}
__device__ __forceinline__ void cp_commit() { asm volatile("cp.async.commit_group;"); }
template <int N>
__device__ __forceinline__ void cp_wait() {
    asm volatile("cp.async.wait_group %0;" :: "n"(N));
}

// ---------------- kernel 0-2: routing ----------------------------------------
__global__ void zero_kernel() {
    if (threadIdx.x < NEXP) g_cnt[threadIdx.x] = 0;
}

__global__ void zero_out_kernel(float4* __restrict__ out) {
    out[blockIdx.x * 256 + threadIdx.x] = make_float4(0.f, 0.f, 0.f, 0.f);
}

__global__ void route_kernel(const float* __restrict__ x, const float* __restrict__ gw) {
    __shared__ float s_gw[NEXP * DIM];
    int tid = threadIdx.x;
    for (int i = tid; i < NEXP * DIM; i += blockDim.x) s_gw[i] = gw[i];
    __syncthreads();

    int warp = tid >> 5, lane = tid & 31;
    int t = blockIdx.x * (blockDim.x >> 5) + warp;
    if (t >= NTOK) return;

    const float* xr = x + (size_t)t * DIM;
    float xv[32];
#pragma unroll
    for (int i = 0; i < 32; i++) xv[i] = xr[i * 32 + lane];

    float logit[NEXP];
#pragma unroll
    for (int e = 0; e < NEXP; e++) {
        float acc = 0.f;
#pragma unroll
        for (int i = 0; i < 32; i++) acc += xv[i] * s_gw[e * DIM + i * 32 + lane];
#pragma unroll
        for (int o = 16; o; o >>= 1) acc += __shfl_xor_sync(0xffffffffu, acc, o);
        logit[e] = acc;
    }

    if (lane == 0) {
        int i0 = 0;
#pragma unroll
        for (int e = 1; e < NEXP; e++) if (logit[e] > logit[i0]) i0 = e;
        int i1 = (i0 == 0) ? 1 : 0;
#pragma unroll
        for (int e = 0; e < NEXP; e++) {
            if (e == i0 || e == i1) continue;
            if (logit[e] > logit[i1]) i1 = e;
        }
        float ee = __expf(logit[i1] - logit[i0]);
        float inv = 1.f / (1.f + ee);
        int p0 = atomicAdd(&g_cnt[i0], 1);
        g_tok[i0 * CAP + p0] = t;  g_wtl[i0 * CAP + p0] = inv;
        int p1 = atomicAdd(&g_cnt[i1], 1);
        g_tok[i1 * CAP + p1] = t;  g_wtl[i1 * CAP + p1] = ee * inv;
    }
}

__global__ void prefix_kernel() {
    if (threadIdx.x == 0) {
        int s = 0;
#pragma unroll
        for (int e = 0; e < NEXP; e++) { g_off[e] = s; s += g_cnt[e]; }
    }
}

// ---------------- kernel 3: weight prep: fp16 convert + transpose to [N][K] ---
template <int WHICH>   // 0: W1 (K=DIM, N=DFF) -> g_W1h;  1: W2 (K=DFF, N=DIM) -> g_W2h
__global__ void wprep_kernel(const float* __restrict__ src) {
    constexpr int K = WHICH ? DFF : DIM;
    constexpr int N = WHICH ? DIM : DFF;
    __shared__ float t[32][33];
    __half* dall = WHICH ? g_W2h : g_W1h;          // device-side symbol
    int e = blockIdx.z;
    const float* s = src + (size_t)e * K * N;
    __half* d = dall + (size_t)e * K * N;
    int nb = blockIdx.x * 32, kb = blockIdx.y * 32;
    int tx = threadIdx.x, ty = threadIdx.y;        // block (32, 8)
#pragma unroll
    for (int j = 0; j < 4; j++)
        t[ty + j * 8][tx] = s[(size_t)(kb + ty + j * 8) * N + nb + tx];
    __syncthreads();
#pragma unroll
    for (int j = 0; j < 4; j++)
        d[(size_t)(nb + ty + j * 8) * K + kb + tx] = __float2half_rn(t[tx][ty + j * 8]);
}

// ---------------- kernel 4: gather x -> fp16 ----------------------------------
__global__ void gather_kernel(const float* __restrict__ x) {
    int e = blockIdx.y, m = blockIdx.x;
    if (m >= g_cnt[e]) return;
    int tok = g_tok[e * CAP + m];
    int row = g_off[e] + m;
    const float4* src = (const float4*)(x + (size_t)tok * DIM);
    int t = threadIdx.x;                           // 128 threads, 8 halves each
    float4 a = src[2 * t], b = src[2 * t + 1];
    union { uint4 u; __half2 h[4]; } pk;
    pk.h[0] = __floats2half2_rn(a.x, a.y);
    pk.h[1] = __floats2half2_rn(a.z, a.w);
    pk.h[2] = __floats2half2_rn(b.x, b.y);
    pk.h[3] = __floats2half2_rn(b.z, b.w);
    *(uint4*)(g_Xh + (size_t)row * DIM + t * 8) = pk.u;
}

// ---------------- kernels 5/6: cp.async + ldmatrix fp16 grouped GEMM ----------
// 512 threads: 16 warps, 2(M) x 8(N), warp tile 64x32. CTA tile 128x256x64,
// 3-stage cp.async.  RS=BK+8 halves keeps LDSM conflict-free.
// MODE 0: Hh = fp16(silu(Xh @ W1 + b1))   (KDIM=DIM,  NDIM=DFF)
// MODE 1: out[tok] += (Hh @ W2 + b2) * wt (KDIM=DFF,  NDIM=DIM)  [atomicAdd]
template <int KDIM, int NDIM, int MODE>
__global__ void __launch_bounds__(512, 1) ffn_gemm(const float* __restrict__ ball,
                                                   float* __restrict__ outp) {
    constexpr int BM = 128, BN = 256, BK = 64, STAGES = 3;
    constexpr int RS = BK + 8;                  // halves: 72 (144B rows)
    constexpr int SAH = BM * RS;                // 9216 halves
    constexpr int SBH = BN * RS;                // 18432 halves
    constexpr int SSH = SAH + SBH;              // 27648 halves = 55296 B / stage
    constexpr int KT = KDIM / BK;
    constexpr int NN = NDIM / BN;
    constexpr int GM = 16;                      // raster group (L2 reuse)

    extern __shared__ __half sm[];

    const __half* Ain = (MODE == 0) ? g_Xh : g_Hh;     // device symbols
    const __half* Wt  = (MODE == 0) ? g_W1h : g_W2h;

    int e = blockIdx.z;
    int cnt = g_cnt[e];
    int per = GM * NN;
    int grp = blockIdx.x / per;
    int rem = blockIdx.x - grp * per;
    int mb = grp * GM + (rem % GM);
    int nb = rem / GM;
    int m0 = mb * BM;
    if (m0 >= cnt) return;
    int n0 = nb * BN;
    int off = g_off[e];

    const __half* Abase = Ain + (size_t)(off + m0) * KDIM;
    const __half* Bbase = Wt + (size_t)e * KDIM * NDIM + (size_t)n0 * KDIM;
    const float* bias = ball + (size_t)e * NDIM;

    int tid = threadIdx.x;
    int warp = tid >> 5, lane = tid & 31;
    int wm = warp & 1, wn = warp >> 1;           // 2 (M) x 8 (N); warp tile 64x32
    int group = lane >> 2, tig = lane & 3;

    uint32_t sbase = (uint32_t)__cvta_generic_to_shared(sm);

    // staging maps (16B = 8-half chunks): A 1024 chunks (2/thr), B 2048 (4/thr)
    const __half* a_src[2];
    uint32_t a_dst[2];
#pragma unroll
    for (int i = 0; i < 2; i++) {
        int c = tid + 512 * i;                   // 128 rows x 8 chunks
        int r = c >> 3, s = c & 7;
        a_src[i] = Abase + (size_t)r * KDIM + s * 8;
        a_dst[i] = (uint32_t)((r * RS + s * 8) * 2);
    }
    const __half* b_src[4];
    uint32_t b_dst[4];
#pragma unroll
    for (int i = 0; i < 4; i++) {
        int c = tid + 512 * i;                   // 256 rows x 8 chunks
        int n = c >> 3, s = c & 7;
        b_src[i] = Bbase + (size_t)n * KDIM + s * 8;
        b_dst[i] = (uint32_t)((SAH + n * RS + s * 8) * 2);
    }

    auto issue = [&](int kt, int stage) {
        uint32_t sb = sbase + (uint32_t)(stage * SSH * 2);
#pragma unroll
        for (int i = 0; i < 2; i++)
            cpasync16(sb + a_dst[i], a_src[i] + (size_t)kt * BK);
#pragma unroll
        for (int i = 0; i < 4; i++)
            cpasync16(sb + b_dst[i], b_src[i] + (size_t)kt * BK);
    };

    // ldmatrix per-thread components
    int lrow = lane & 15;                        // row within 16-block
    int lchk = (lane >> 4) * 8;                  // k offset in halves: 0 / 8

    float acc[4][4][4];
#pragma unroll
    for (int mi = 0; mi < 4; mi++)
#pragma unroll
        for (int ni = 0; ni < 4; ni++)
#pragma unroll
            for (int r = 0; r < 4; r++) acc[mi][ni][r] = 0.f;

    issue(0, 0); cp_commit();
    issue(1, 1); cp_commit();

    for (int kt = 0; kt < KT; kt++) {
        cp_wait<1>();
        __syncthreads();                         // stage kt resident
        if (kt + 2 < KT) issue(kt + 2, (kt + 2) % STAGES);
        cp_commit();

        uint32_t sA = sbase + (uint32_t)((kt % STAGES) * SSH * 2);
        uint32_t sB = sA + (uint32_t)(SAH * 2);
#pragma unroll
        for (int ks = 0; ks < 4; ks++) {         // K=16 per step
            int kk = ks * 16;
            unsigned af[4][4], bf[4][2];
#pragma unroll
            for (int mi = 0; mi < 4; mi++) {
                uint32_t addr = sA + (uint32_t)(((wm * 64 + mi * 16 + lrow) * RS
                                                + kk + lchk) * 2);
                ldsm_x4(af[mi][0], af[mi][1], af[mi][2], af[mi][3], addr);
            }
#pragma unroll
            for (int nj = 0; nj < 2; nj++) {
                uint32_t addr = sB + (uint32_t)(((wn * 32 + nj * 16 + lrow) * RS
                                                + kk + lchk) * 2);
                unsigned r0, r1, r2, r3;
                ldsm_x4(r0, r1, r2, r3, addr);
                bf[2 * nj][0]     = r0;  bf[2 * nj][1]     = r2;   // n 0-7
                bf[2 * nj + 1][0] = r1;  bf[2 * nj + 1][1] = r3;   // n 8-15
            }
#pragma unroll
            for (int mi = 0; mi < 4; mi++)
#pragma unroll
                for (int ni = 0; ni < 4; ni++)
                    mma_f16(acc[mi][ni], af[mi], bf[ni]);
        }
        __syncthreads();
    }

    // epilogue (fp32 math; MODE 0 -> fp16 H, MODE 1 -> atomicAdd to out)
#pragma unroll
    for (int mi = 0; mi < 4; mi++) {
#pragma unroll
        for (int half = 0; half < 2; half++) {
            int m = m0 + wm * 64 + mi * 16 + group + half * 8;
            if (m >= cnt) continue;
            if (MODE == 0) {
                size_t rowbase = (size_t)(off + m) * NDIM;
#pragma unroll
                for (int ni = 0; ni < 4; ni++) {
                    int c = n0 + wn * 32 + ni * 8 + tig * 2;
                    float v0 = acc[mi][ni][half * 2 + 0] + bias[c];
                    float v1 = acc[mi][ni][half * 2 + 1] + bias[c + 1];
                    v0 = v0 / (1.f + __expf(-v0));
                    v1 = v1 / (1.f + __expf(-v1));
                    *(__half2*)(g_Hh + rowbase + c) = __floats2half2_rn(v0, v1);
                }
            } else {
                int tok = g_tok[e * CAP + m];
                float w = g_wtl[e * CAP + m];
                float* orow = outp + (size_t)tok * NDIM;
#pragma unroll
                for (int ni = 0; ni < 4; ni++) {
                    int c = n0 + wn * 32 + ni * 8 + tig * 2;
                    // exactly 2 contributions per element, fp32 add commutative
                    atomicAdd(&orow[c],     (acc[mi][ni][half * 2 + 0] + bias[c]) * w);
                    atomicAdd(&orow[c + 1], (acc[mi][ni][half * 2 + 1] + bias[c + 1]) * w);
                }
            }
        }
    }
}

// ---------------- launch ------------------------------------------------------
extern "C" void kernel_launch(void* const* d_in, const int* in_sizes, int n_in,
                              void* d_out, int out_size) {
    const float* x  = (const float*)d_in[0];
    const float* gw = (const float*)d_in[1];
    const float* W1 = (const float*)d_in[2];
    const float* b1 = (const float*)d_in[3];
    const float* W2 = (const float*)d_in[4];
    const float* b2 = (const float*)d_in[5];
    float* out = (float*)d_out;

    // opt into >48KB dynamic smem (attribute call, not an allocation)
    constexpr int GEMM_SMEM = 3 * (128 * 72 + 256 * 72) * 2;   // 165,888 B
    cudaFuncSetAttribute(ffn_gemm<DIM, DFF, 0>,
                         cudaFuncAttributeMaxDynamicSharedMemorySize, GEMM_SMEM);
    cudaFuncSetAttribute(ffn_gemm<DFF, DIM, 1>,
                         cudaFuncAttributeMaxDynamicSharedMemorySize, GEMM_SMEM);

    zero_kernel<<<1, 32>>>();
    zero_out_kernel<<<(NTOK * (DIM / 4)) / 256, 256>>>((float4*)out);
    route_kernel<<<NTOK / 8, 256>>>(x, gw);
    prefix_kernel<<<1, 32>>>();

    // weight prep: fp16 convert + transpose to [N][K]
    wprep_kernel<0><<<dim3(DFF / 32, DIM / 32, NEXP), dim3(32, 8)>>>(W1);
    wprep_kernel<1><<<dim3(DIM / 32, DFF / 32, NEXP), dim3(32, 8)>>>(W2);
    gather_kernel<<<dim3(CAP, NEXP), 128>>>(x);

    // GEMM1: (CAP/128) * (DFF/256) = 128 * 16 blocks, z = experts
    ffn_gemm<DIM, DFF, 0><<<dim3((CAP / 128) * (DFF / 256), 1, NEXP), 512, GEMM_SMEM>>>(b1, nullptr);
    // GEMM2: accumulates straight into out (two slots per token, commutative)
    ffn_gemm<DFF, DIM, 1><<<dim3((CAP / 128) * (DIM / 256), 1, NEXP), 512, GEMM_SMEM>>>(b2, out);
}

// round 15
// speedup vs baseline: 1.0560x; 1.0060x over previous
#include <cuda_runtime.h>
#include <cuda_fp16.h>
#include <cstdint>
#include <cstddef>

// Problem constants
#define NEXP 8
#define TOPK 2
#define DIM 1024
#define DFF 4096
#define NTOK 16384          // B*S
#define CAP  16384          // per-expert capacity
#define RTOT (NTOK * TOPK)  // 32768 expert-rows
#define PADR 128            // row padding for tile overrun

// ---------------- scratch (device globals; DEVICE-CODE REFERENCES ONLY) ------
// RULE (rounds 2-5): never pass these symbols as host-side kernel args — the
// host shadow is ATS-readable on GB300 and silently reads zeros.
__device__ int    g_cnt[NEXP];
__device__ int    g_off[NEXP];
__device__ int    g_tok[NEXP * CAP];
__device__ float  g_wtl[NEXP * CAP];
__device__ __half g_Xh[(size_t)(RTOT + PADR) * DIM];   // gathered x, fp16
__device__ __half g_Hh[(size_t)(RTOT + PADR) * DFF];   // hidden scratch, fp16
__device__ __half g_W1h[(size_t)NEXP * DIM * DFF];     // W1^T: [DFF][DIM], fp16
__device__ __half g_W2h[(size_t)NEXP * DFF * DIM];     // W2^T: [DIM][DFF], fp16

// ---------------- helpers ----------------------------------------------------
__device__ __forceinline__ void mma_f16(float c[4], const unsigned a[4], const unsigned b[2]) {
    asm volatile(
        "mma.sync.aligned.m16n8k16.row.col.f32.f16.f16.f32 "
        "{%0,%1,%2,%3}, {%4,%5,%6,%7}, {%8,%9}, {%0,%1,%2,%3};\n"
        : "+f"(c[0]), "+f"(c[1]), "+f"(c[2]), "+f"(c[3])
        : "r"(a[0]), "r"(a[1]), "r"(a[2]), "r"(a[3]), "r"(b[0]), "r"(b[1]));
}
__device__ __forceinline__ void ldsm_x4(unsigned& r0, unsigned& r1, unsigned& r2,
                                        unsigned& r3, uint32_t addr) {
    asm volatile("ldmatrix.sync.aligned.m8n8.x4.shared.b16 {%0,%1,%2,%3}, [%4];"
                 : "=r"(r0), "=r"(r1), "=r"(r2), "=r"(r3) : "r"(addr));
}
__device__ __forceinline__ void cpasync16(uint32_t d, const void* s) {
    asm volatile("cp.async.cg.shared.global [%0], [%1], 16;" :: "r"(d), "l"(s));
}
__device__ __forceinline__ void cp_commit() { asm volatile("cp.async.commit_group;"); }
template <int N>
__device__ __forceinline__ void cp_wait() {
    asm volatile("cp.async.wait_group %0;" :: "n"(N));
}

// ---------------- kernel 0-2: routing ----------------------------------------
__global__ void zero_kernel() {
    if (threadIdx.x < NEXP) g_cnt[threadIdx.x] = 0;
}

__global__ void zero_out_kernel(float4* __restrict__ out) {
    out[blockIdx.x * 256 + threadIdx.x] = make_float4(0.f, 0.f, 0.f, 0.f);
}

__global__ void route_kernel(const float* __restrict__ x, const float* __restrict__ gw) {
    __shared__ float s_gw[NEXP * DIM];
    int tid = threadIdx.x;
    for (int i = tid; i < NEXP * DIM; i += blockDim.x) s_gw[i] = gw[i];
    __syncthreads();

    int warp = tid >> 5, lane = tid & 31;
    int t = blockIdx.x * (blockDim.x >> 5) + warp;
    if (t >= NTOK) return;

    const float* xr = x + (size_t)t * DIM;
    float xv[32];
#pragma unroll
    for (int i = 0; i < 32; i++) xv[i] = xr[i * 32 + lane];

    float logit[NEXP];
#pragma unroll
    for (int e = 0; e < NEXP; e++) {
        float acc = 0.f;
#pragma unroll
        for (int i = 0; i < 32; i++) acc += xv[i] * s_gw[e * DIM + i * 32 + lane];
#pragma unroll
        for (int o = 16; o; o >>= 1) acc += __shfl_xor_sync(0xffffffffu, acc, o);
        logit[e] = acc;
    }

    if (lane == 0) {
        int i0 = 0;
#pragma unroll
        for (int e = 1; e < NEXP; e++) if (logit[e] > logit[i0]) i0 = e;
        int i1 = (i0 == 0) ? 1 : 0;
#pragma unroll
        for (int e = 0; e < NEXP; e++) {
            if (e == i0 || e == i1) continue;
            if (logit[e] > logit[i1]) i1 = e;
        }
        float ee = __expf(logit[i1] - logit[i0]);
        float inv = 1.f / (1.f + ee);
        int p0 = atomicAdd(&g_cnt[i0], 1);
        g_tok[i0 * CAP + p0] = t;  g_wtl[i0 * CAP + p0] = inv;
        int p1 = atomicAdd(&g_cnt[i1], 1);
        g_tok[i1 * CAP + p1] = t;  g_wtl[i1 * CAP + p1] = ee * inv;
    }
}

__global__ void prefix_kernel() {
    if (threadIdx.x == 0) {
        int s = 0;
#pragma unroll
        for (int e = 0; e < NEXP; e++) { g_off[e] = s; s += g_cnt[e]; }
    }
}

// ---------------- kernel 3: weight prep: fp16 convert + transpose to [N][K] ---
template <int WHICH>   // 0: W1 (K=DIM, N=DFF) -> g_W1h;  1: W2 (K=DFF, N=DIM) -> g_W2h
__global__ void wprep_kernel(const float* __restrict__ src) {
    constexpr int K = WHICH ? DFF : DIM;
    constexpr int N = WHICH ? DIM : DFF;
    __shared__ float t[32][33];
    __half* dall = WHICH ? g_W2h : g_W1h;          // device-side symbol
    int e = blockIdx.z;
    const float* s = src + (size_t)e * K * N;
    __half* d = dall + (size_t)e * K * N;
    int nb = blockIdx.x * 32, kb = blockIdx.y * 32;
    int tx = threadIdx.x, ty = threadIdx.y;        // block (32, 8)
#pragma unroll
    for (int j = 0; j < 4; j++)
        t[ty + j * 8][tx] = s[(size_t)(kb + ty + j * 8) * N + nb + tx];
    __syncthreads();
#pragma unroll
    for (int j = 0; j < 4; j++)
        d[(size_t)(nb + ty + j * 8) * K + kb + tx] = __float2half_rn(t[tx][ty + j * 8]);
}

// ---------------- kernel 4: gather x -> fp16 ----------------------------------
__global__ void gather_kernel(const float* __restrict__ x) {
    int e = blockIdx.y, m = blockIdx.x;
    if (m >= g_cnt[e]) return;
    int tok = g_tok[e * CAP + m];
    int row = g_off[e] + m;
    const float4* src = (const float4*)(x + (size_t)tok * DIM);
    int t = threadIdx.x;                           // 128 threads, 8 halves each
    float4 a = src[2 * t], b = src[2 * t + 1];
    union { uint4 u; __half2 h[4]; } pk;
    pk.h[0] = __floats2half2_rn(a.x, a.y);
    pk.h[1] = __floats2half2_rn(a.z, a.w);
    pk.h[2] = __floats2half2_rn(b.x, b.y);
    pk.h[3] = __floats2half2_rn(b.z, b.w);
    *(uint4*)(g_Xh + (size_t)row * DIM + t * 8) = pk.u;
}

// ---------------- kernels 5/6: cp.async + ldmatrix fp16 grouped GEMM ----------
// 512 threads: 16 warps, 2(M) x 8(N), warp tile 64x32. CTA tile 128x256x64,
// 4-stage cp.async, ONE barrier per k-tile (issue placed after the sync:
// stage (kt+3)%4 was last read at kt-1, and those reads precede every
// thread's arrival at this iteration's sync -> no race).
// MODE 0: Hh = fp16(silu(Xh @ W1 + b1))   (KDIM=DIM,  NDIM=DFF)
// MODE 1: out[tok] += (Hh @ W2 + b2) * wt (KDIM=DFF,  NDIM=DIM)  [atomicAdd]
template <int KDIM, int NDIM, int MODE>
__global__ void __launch_bounds__(512, 1) ffn_gemm(const float* __restrict__ ball,
                                                   float* __restrict__ outp) {
    constexpr int BM = 128, BN = 256, BK = 64, STAGES = 4;
    constexpr int RS = BK + 8;                  // halves: 72 (144B rows)
    constexpr int SAH = BM * RS;                // 9216 halves
    constexpr int SBH = BN * RS;                // 18432 halves
    constexpr int SSH = SAH + SBH;              // 27648 halves = 55296 B / stage
    constexpr int KT = KDIM / BK;
    constexpr int NN = NDIM / BN;
    constexpr int GM = 16;                      // raster group (L2 reuse)

    extern __shared__ __half sm[];

    const __half* Ain = (MODE == 0) ? g_Xh : g_Hh;     // device symbols
    const __half* Wt  = (MODE == 0) ? g_W1h : g_W2h;

    int e = blockIdx.z;
    int cnt = g_cnt[e];
    int per = GM * NN;
    int grp = blockIdx.x / per;
    int rem = blockIdx.x - grp * per;
    int mb = grp * GM + (rem % GM);
    int nb = rem / GM;
    int m0 = mb * BM;
    if (m0 >= cnt) return;
    int n0 = nb * BN;
    int off = g_off[e];

    const __half* Abase = Ain + (size_t)(off + m0) * KDIM;
    const __half* Bbase = Wt + (size_t)e * KDIM * NDIM + (size_t)n0 * KDIM;
    const float* bias = ball + (size_t)e * NDIM;

    int tid = threadIdx.x;
    int warp = tid >> 5, lane = tid & 31;
    int wm = warp & 1, wn = warp >> 1;           // 2 (M) x 8 (N); warp tile 64x32
    int group = lane >> 2, tig = lane & 3;

    uint32_t sbase = (uint32_t)__cvta_generic_to_shared(sm);

    // staging maps (16B = 8-half chunks): A 1024 chunks (2/thr), B 2048 (4/thr)
    const __half* a_src[2];
    uint32_t a_dst[2];
#pragma unroll
    for (int i = 0; i < 2; i++) {
        int c = tid + 512 * i;                   // 128 rows x 8 chunks
        int r = c >> 3, s = c & 7;
        a_src[i] = Abase + (size_t)r * KDIM + s * 8;
        a_dst[i] = (uint32_t)((r * RS + s * 8) * 2);
    }
    const __half* b_src[4];
    uint32_t b_dst[4];
#pragma unroll
    for (int i = 0; i < 4; i++) {
        int c = tid + 512 * i;                   // 256 rows x 8 chunks
        int n = c >> 3, s = c & 7;
        b_src[i] = Bbase + (size_t)n * KDIM + s * 8;
        b_dst[i] = (uint32_t)((SAH + n * RS + s * 8) * 2);
    }

    auto issue = [&](int kt, int stage) {
        uint32_t sb = sbase + (uint32_t)(stage * SSH * 2);
#pragma unroll
        for (int i = 0; i < 2; i++)
            cpasync16(sb + a_dst[i], a_src[i] + (size_t)kt * BK);
#pragma unroll
        for (int i = 0; i < 4; i++)
            cpasync16(sb + b_dst[i], b_src[i] + (size_t)kt * BK);
    };

    // ldmatrix per-thread components
    int lrow = lane & 15;                        // row within 16-block
    int lchk = (lane >> 4) * 8;                  // k offset in halves: 0 / 8

    float acc[4][4][4];
#pragma unroll
    for (int mi = 0; mi < 4; mi++)
#pragma unroll
        for (int ni = 0; ni < 4; ni++)
#pragma unroll
            for (int r = 0; r < 4; r++) acc[mi][ni][r] = 0.f;

    issue(0, 0); cp_commit();
    issue(1, 1); cp_commit();
    issue(2, 2); cp_commit();

    for (int kt = 0; kt < KT; kt++) {
        cp_wait<2>();                            // stage kt arrived (<=2 in flight)
        __syncthreads();                         // visible to all warps; also
                                                 // retires all reads of kt-1
        if (kt + 3 < KT) issue(kt + 3, (kt + 3) % STAGES);   // safe post-sync
        cp_commit();

        uint32_t sA = sbase + (uint32_t)((kt % STAGES) * SSH * 2);
        uint32_t sB = sA + (uint32_t)(SAH * 2);
#pragma unroll
        for (int ks = 0; ks < 4; ks++) {         // K=16 per step
            int kk = ks * 16;
            unsigned af[4][4], bf[4][2];
#pragma unroll
            for (int mi = 0; mi < 4; mi++) {
                uint32_t addr = sA + (uint32_t)(((wm * 64 + mi * 16 + lrow) * RS
                                                + kk + lchk) * 2);
                ldsm_x4(af[mi][0], af[mi][1], af[mi][2], af[mi][3], addr);
            }
#pragma unroll
            for (int nj = 0; nj < 2; nj++) {
                uint32_t addr = sB + (uint32_t)(((wn * 32 + nj * 16 + lrow) * RS
                                                + kk + lchk) * 2);
                unsigned r0, r1, r2, r3;
                ldsm_x4(r0, r1, r2, r3, addr);
                bf[2 * nj][0]     = r0;  bf[2 * nj][1]     = r2;   // n 0-7
                bf[2 * nj + 1][0] = r1;  bf[2 * nj + 1][1] = r3;   // n 8-15
            }
#pragma unroll
            for (int mi = 0; mi < 4; mi++)
#pragma unroll
                for (int ni = 0; ni < 4; ni++)
                    mma_f16(acc[mi][ni], af[mi], bf[ni]);
        }
        // no bottom barrier: next iteration's top sync provides the fence
    }

    // epilogue (fp32 math; MODE 0 -> fp16 H, MODE 1 -> atomicAdd to out)
#pragma unroll
    for (int mi = 0; mi < 4; mi++) {
#pragma unroll
        for (int half = 0; half < 2; half++) {
            int m = m0 + wm * 64 + mi * 16 + group + half * 8;
            if (m >= cnt) continue;
            if (MODE == 0) {
                size_t rowbase = (size_t)(off + m) * NDIM;
#pragma unroll
                for (int ni = 0; ni < 4; ni++) {
                    int c = n0 + wn * 32 + ni * 8 + tig * 2;
                    float v0 = acc[mi][ni][half * 2 + 0] + bias[c];
                    float v1 = acc[mi][ni][half * 2 + 1] + bias[c + 1];
                    v0 = v0 / (1.f + __expf(-v0));
                    v1 = v1 / (1.f + __expf(-v1));
                    *(__half2*)(g_Hh + rowbase + c) = __floats2half2_rn(v0, v1);
                }
            } else {
                int tok = g_tok[e * CAP + m];
                float w = g_wtl[e * CAP + m];
                float* orow = outp + (size_t)tok * NDIM;
#pragma unroll
                for (int ni = 0; ni < 4; ni++) {
                    int c = n0 + wn * 32 + ni * 8 + tig * 2;
                    // exactly 2 contributions per element, fp32 add commutative
                    atomicAdd(&orow[c],     (acc[mi][ni][half * 2 + 0] + bias[c]) * w);
                    atomicAdd(&orow[c + 1], (acc[mi][ni][half * 2 + 1] + bias[c + 1]) * w);
                }
            }
        }
    }
}

// ---------------- launch ------------------------------------------------------
extern "C" void kernel_launch(void* const* d_in, const int* in_sizes, int n_in,
                              void* d_out, int out_size) {
    const float* x  = (const float*)d_in[0];
    const float* gw = (const float*)d_in[1];
    const float* W1 = (const float*)d_in[2];
    const float* b1 = (const float*)d_in[3];
    const float* W2 = (const float*)d_in[4];
    const float* b2 = (const float*)d_in[5];
    float* out = (float*)d_out;

    // opt into >48KB dynamic smem (attribute call, not an allocation)
    constexpr int GEMM_SMEM = 4 * (128 * 72 + 256 * 72) * 2;   // 221,184 B
    cudaFuncSetAttribute(ffn_gemm<DIM, DFF, 0>,
                         cudaFuncAttributeMaxDynamicSharedMemorySize, GEMM_SMEM);
    cudaFuncSetAttribute(ffn_gemm<DFF, DIM, 1>,
                         cudaFuncAttributeMaxDynamicSharedMemorySize, GEMM_SMEM);

    zero_kernel<<<1, 32>>>();
    zero_out_kernel<<<(NTOK * (DIM / 4)) / 256, 256>>>((float4*)out);
    route_kernel<<<NTOK / 8, 256>>>(x, gw);
    prefix_kernel<<<1, 32>>>();

    // weight prep: fp16 convert + transpose to [N][K]
    wprep_kernel<0><<<dim3(DFF / 32, DIM / 32, NEXP), dim3(32, 8)>>>(W1);
    wprep_kernel<1><<<dim3(DIM / 32, DFF / 32, NEXP), dim3(32, 8)>>>(W2);
    gather_kernel<<<dim3(CAP, NEXP), 128>>>(x);

    // GEMM1: (CAP/128) * (DFF/256) = 128 * 16 blocks, z = experts
    ffn_gemm<DIM, DFF, 0><<<dim3((CAP / 128) * (DFF / 256), 1, NEXP), 512, GEMM_SMEM>>>(b1, nullptr);
    // GEMM2: accumulates straight into out (two slots per token, commutative)
    ffn_gemm<DFF, DIM, 1><<<dim3((CAP / 128) * (DIM / 256), 1, NEXP), 512, GEMM_SMEM>>>(b2, out);
}

// round 16
// speedup vs baseline: 1.2509x; 1.1846x over previous
#include <cuda_runtime.h>
#include <cuda.h>
#include <cuda_fp16.h>
#include <cstdint>
#include <cstddef>

// Problem constants
#define NEXP 8
#define TOPK 2
#define DIM 1024
#define DFF 4096
#define NTOK 16384          // B*S
#define CAP  16384          // per-expert capacity
#define RTOT (NTOK * TOPK)  // 32768 expert-rows
#define PADR 128            // row padding for tile overrun

// ---------------- scratch (device globals; DEVICE-CODE REFERENCES ONLY) ------
// RULE (rounds 2-5): never pass these symbols as host-side kernel args — the
// host shadow is ATS-readable on GB300 and silently reads zeros. (Taking their
// device address via cudaGetSymbolAddress for TMA descriptors is fine.)
__device__ int    g_cnt[NEXP];
__device__ int    g_off[NEXP];
__device__ int    g_tok[NEXP * CAP];
__device__ float  g_wtl[NEXP * CAP];
__device__ __half g_Xh[(size_t)(RTOT + PADR) * DIM];   // gathered x, fp16
__device__ __half g_Hh[(size_t)(RTOT + PADR) * DFF];   // hidden scratch, fp16
__device__ __half g_W1h[(size_t)NEXP * DIM * DFF];     // W1^T: [DFF][DIM], fp16
__device__ __half g_W2h[(size_t)NEXP * DFF * DIM];     // W2^T: [DIM][DFF], fp16

// ---------------- helpers ----------------------------------------------------
__device__ __forceinline__ void mma_f16(float c[4], const unsigned a[4], const unsigned b[2]) {
    asm volatile(
        "mma.sync.aligned.m16n8k16.row.col.f32.f16.f16.f32 "
        "{%0,%1,%2,%3}, {%4,%5,%6,%7}, {%8,%9}, {%0,%1,%2,%3};\n"
        : "+f"(c[0]), "+f"(c[1]), "+f"(c[2]), "+f"(c[3])
        : "r"(a[0]), "r"(a[1]), "r"(a[2]), "r"(a[3]), "r"(b[0]), "r"(b[1]));
}
__device__ __forceinline__ void ldsm_x4(unsigned& r0, unsigned& r1, unsigned& r2,
                                        unsigned& r3, uint32_t addr) {
    asm volatile("ldmatrix.sync.aligned.m8n8.x4.shared.b16 {%0,%1,%2,%3}, [%4];"
                 : "=r"(r0), "=r"(r1), "=r"(r2), "=r"(r3) : "r"(addr));
}
__device__ __forceinline__ void mbar_init(uint32_t a, uint32_t cnt) {
    asm volatile("mbarrier.init.shared.b64 [%0], %1;" :: "r"(a), "r"(cnt) : "memory");
}
__device__ __forceinline__ void mbar_expect_tx(uint32_t a, uint32_t bytes) {
    asm volatile("mbarrier.arrive.expect_tx.shared.b64 _, [%0], %1;"
                 :: "r"(a), "r"(bytes) : "memory");
}
__device__ __forceinline__ void mbar_wait(uint32_t a, uint32_t parity) {
    asm volatile(
        "{\n\t.reg .pred P;\n"
        "LW_%=:\n\t"
        "mbarrier.try_wait.parity.acquire.cta.shared::cta.b64 P, [%0], %1;\n\t"
        "@!P bra LW_%=;\n\t}"
        :: "r"(a), "r"(parity) : "memory");
}
__device__ __forceinline__ void tma_ld_2d(uint32_t dst, const void* map,
                                          int c0, int c1, uint32_t mbar) {
    asm volatile(
        "cp.async.bulk.tensor.2d.shared::cta.global.tile.mbarrier::complete_tx::bytes "
        "[%0], [%1, {%2, %3}], [%4];"
        :: "r"(dst), "l"(map), "r"(c0), "r"(c1), "r"(mbar) : "memory");
}

// ---------------- kernel 0-2: routing ----------------------------------------
__global__ void zero_kernel() {
    if (threadIdx.x < NEXP) g_cnt[threadIdx.x] = 0;
}

__global__ void zero_out_kernel(float4* __restrict__ out) {
    out[blockIdx.x * 256 + threadIdx.x] = make_float4(0.f, 0.f, 0.f, 0.f);
}

__global__ void route_kernel(const float* __restrict__ x, const float* __restrict__ gw) {
    __shared__ float s_gw[NEXP * DIM];
    int tid = threadIdx.x;
    for (int i = tid; i < NEXP * DIM; i += blockDim.x) s_gw[i] = gw[i];
    __syncthreads();

    int warp = tid >> 5, lane = tid & 31;
    int t = blockIdx.x * (blockDim.x >> 5) + warp;
    if (t >= NTOK) return;

    const float* xr = x + (size_t)t * DIM;
    float xv[32];
#pragma unroll
    for (int i = 0; i < 32; i++) xv[i] = xr[i * 32 + lane];

    float logit[NEXP];
#pragma unroll
    for (int e = 0; e < NEXP; e++) {
        float acc = 0.f;
#pragma unroll
        for (int i = 0; i < 32; i++) acc += xv[i] * s_gw[e * DIM + i * 32 + lane];
#pragma unroll
        for (int o = 16; o; o >>= 1) acc += __shfl_xor_sync(0xffffffffu, acc, o);
        logit[e] = acc;
    }

    if (lane == 0) {
        int i0 = 0;
#pragma unroll
        for (int e = 1; e < NEXP; e++) if (logit[e] > logit[i0]) i0 = e;
        int i1 = (i0 == 0) ? 1 : 0;
#pragma unroll
        for (int e = 0; e < NEXP; e++) {
            if (e == i0 || e == i1) continue;
            if (logit[e] > logit[i1]) i1 = e;
        }
        float ee = __expf(logit[i1] - logit[i0]);
        float inv = 1.f / (1.f + ee);
        int p0 = atomicAdd(&g_cnt[i0], 1);
        g_tok[i0 * CAP + p0] = t;  g_wtl[i0 * CAP + p0] = inv;
        int p1 = atomicAdd(&g_cnt[i1], 1);
        g_tok[i1 * CAP + p1] = t;  g_wtl[i1 * CAP + p1] = ee * inv;
    }
}

__global__ void prefix_kernel() {
    if (threadIdx.x == 0) {
        int s = 0;
#pragma unroll
        for (int e = 0; e < NEXP; e++) { g_off[e] = s; s += g_cnt[e]; }
    }
}

// ---------------- kernel 3: weight prep: fp16 convert + transpose to [N][K] ---
template <int WHICH>   // 0: W1 (K=DIM, N=DFF) -> g_W1h;  1: W2 (K=DFF, N=DIM) -> g_W2h
__global__ void wprep_kernel(const float* __restrict__ src) {
    constexpr int K = WHICH ? DFF : DIM;
    constexpr int N = WHICH ? DIM : DFF;
    __shared__ float t[32][33];
    __half* dall = WHICH ? g_W2h : g_W1h;          // device-side symbol
    int e = blockIdx.z;
    const float* s = src + (size_t)e * K * N;
    __half* d = dall + (size_t)e * K * N;
    int nb = blockIdx.x * 32, kb = blockIdx.y * 32;
    int tx = threadIdx.x, ty = threadIdx.y;        // block (32, 8)
#pragma unroll
    for (int j = 0; j < 4; j++)
        t[ty + j * 8][tx] = s[(size_t)(kb + ty + j * 8) * N + nb + tx];
    __syncthreads();
#pragma unroll
    for (int j = 0; j < 4; j++)
        d[(size_t)(nb + ty + j * 8) * K + kb + tx] = __float2half_rn(t[tx][ty + j * 8]);
}

// ---------------- kernel 4: gather x -> fp16 ----------------------------------
__global__ void gather_kernel(const float* __restrict__ x) {
    int e = blockIdx.y, m = blockIdx.x;
    if (m >= g_cnt[e]) return;
    int tok = g_tok[e * CAP + m];
    int row = g_off[e] + m;
    const float4* src = (const float4*)(x + (size_t)tok * DIM);
    int t = threadIdx.x;                           // 128 threads, 8 halves each
    float4 a = src[2 * t], b = src[2 * t + 1];
    union { uint4 u; __half2 h[4]; } pk;
    pk.h[0] = __floats2half2_rn(a.x, a.y);
    pk.h[1] = __floats2half2_rn(a.z, a.w);
    pk.h[2] = __floats2half2_rn(b.x, b.y);
    pk.h[3] = __floats2half2_rn(b.z, b.w);
    *(uint4*)(g_Xh + (size_t)row * DIM + t * 8) = pk.u;
}

// ---------------- kernels 5/6: TMA + ldmatrix fp16 grouped GEMM ---------------
// 512 threads: 16 warps, 2(M) x 8(N), warp tile 64x32. CTA tile 128x256x64.
// Tiles land via cp.async.bulk.tensor.2d (SW128, 128B rows = BK*2) into a
// 4-stage ring; one mbarrier (count=1, expect_tx=49152B) per stage; the single
// __syncthreads per kt retires stage reads before reissue (R15 protocol).
// ldmatrix addresses apply the SW128 XOR: chunk ^= (row & 7).
// MODE 0: Hh = fp16(silu(Xh @ W1 + b1))   (KDIM=DIM,  NDIM=DFF)
// MODE 1: out[tok] += (Hh @ W2 + b2) * wt (KDIM=DFF,  NDIM=DIM)  [atomicAdd]
template <int KDIM, int NDIM, int MODE>
__global__ void __launch_bounds__(512, 1) ffn_gemm(const float* __restrict__ ball,
                                                   float* __restrict__ outp,
                                                   const __grid_constant__ CUtensorMap mapA,
                                                   const __grid_constant__ CUtensorMap mapB) {
    constexpr int BM = 128, BN = 256, BK = 64, STAGES = 4;
    constexpr int ABYTES = BM * 128;            // 16384 (128B rows, SW128)
    constexpr int BBYTES = BN * 128;            // 32768
    constexpr int STGB = ABYTES + BBYTES;       // 49152 per stage
    constexpr int KT = KDIM / BK;
    constexpr int NN = NDIM / BN;
    constexpr int GM = 16;                      // raster group (L2 reuse)

    extern __shared__ __align__(16) char smraw[];
    uint32_t sbase = (uint32_t)__cvta_generic_to_shared(smraw);
    uint32_t mb = sbase;                                    // 4 mbarriers (8B each)
    uint32_t ab = (sbase + 32 + 1023) & ~1023u;             // 1024-aligned stages

    int e = blockIdx.z;
    int cnt = g_cnt[e];
    int per = GM * NN;
    int grp = blockIdx.x / per;
    int rem = blockIdx.x - grp * per;
    int mbk = grp * GM + (rem % GM);
    int nb = rem / GM;
    int m0 = mbk * BM;
    if (m0 >= cnt) return;
    int n0 = nb * BN;
    int off = g_off[e];

    const float* bias = ball + (size_t)e * NDIM;
    int arow0 = off + m0;                       // A row coord (gathered rows)
    int brow0 = e * NDIM + n0;                  // W^T row coord

    int tid = threadIdx.x;
    int warp = tid >> 5, lane = tid & 31;
    int wm = warp & 1, wn = warp >> 1;          // 2 (M) x 8 (N); warp tile 64x32
    int group = lane >> 2, tig = lane & 3;
    int lrow = lane & 15, lhi = lane >> 4;      // ldmatrix row / k-half select

    if (tid == 0) {
#pragma unroll
        for (int s = 0; s < STAGES; s++) mbar_init(mb + 8 * s, 1);
    }
    __syncthreads();                            // init visible before any wait

    auto issue = [&](int kt) {
        int st = kt & 3;
        uint32_t base = ab + (uint32_t)st * STGB;
        mbar_expect_tx(mb + 8 * st, STGB);
        tma_ld_2d(base,          &mapA, kt * BK, arow0, mb + 8 * st);
        tma_ld_2d(base + ABYTES, &mapB, kt * BK, brow0, mb + 8 * st);
    };

    if (tid == 0) { issue(0); issue(1); issue(2); }

    float acc[4][4][4];
#pragma unroll
    for (int mi = 0; mi < 4; mi++)
#pragma unroll
        for (int ni = 0; ni < 4; ni++)
#pragma unroll
            for (int r = 0; r < 4; r++) acc[mi][ni][r] = 0.f;

    for (int kt = 0; kt < KT; kt++) {
        int st = kt & 3;
        mbar_wait(mb + 8 * st, (kt >> 2) & 1);  // stage kt data arrived
        __syncthreads();                        // all warps past wait; reads of
                                                // stage kt-1 retired (R15 proof)
        if (tid == 0 && kt + 3 < KT) issue(kt + 3);   // reuses stage (kt-1)&3

        uint32_t sA = ab + (uint32_t)st * STGB;
        uint32_t sB = sA + ABYTES;
#pragma unroll
        for (int ks = 0; ks < 4; ks++) {        // K=16 per step
            int c = ks * 2 + lhi;               // 16B chunk index (0..7)
            unsigned af[4][4], bf[4][2];
#pragma unroll
            for (int mi = 0; mi < 4; mi++) {
                int r = wm * 64 + mi * 16 + lrow;
                uint32_t addr = sA + (uint32_t)(r * 128 + ((c ^ (r & 7)) << 4));
                ldsm_x4(af[mi][0], af[mi][1], af[mi][2], af[mi][3], addr);
            }
#pragma unroll
            for (int nj = 0; nj < 2; nj++) {
                int r = wn * 32 + nj * 16 + lrow;
                uint32_t addr = sB + (uint32_t)(r * 128 + ((c ^ (r & 7)) << 4));
                unsigned r0, r1, r2, r3;
                ldsm_x4(r0, r1, r2, r3, addr);
                bf[2 * nj][0]     = r0;  bf[2 * nj][1]     = r2;   // n 0-7
                bf[2 * nj + 1][0] = r1;  bf[2 * nj + 1][1] = r3;   // n 8-15
            }
#pragma unroll
            for (int mi = 0; mi < 4; mi++)
#pragma unroll
                for (int ni = 0; ni < 4; ni++)
                    mma_f16(acc[mi][ni], af[mi], bf[ni]);
        }
    }

    // epilogue (fp32 math; MODE 0 -> fp16 H, MODE 1 -> atomicAdd to out)
#pragma unroll
    for (int mi = 0; mi < 4; mi++) {
#pragma unroll
        for (int half = 0; half < 2; half++) {
            int m = m0 + wm * 64 + mi * 16 + group + half * 8;
            if (m >= cnt) continue;
            if (MODE == 0) {
                size_t rowbase = (size_t)(off + m) * NDIM;
#pragma unroll
                for (int ni = 0; ni < 4; ni++) {
                    int c = n0 + wn * 32 + ni * 8 + tig * 2;
                    float v0 = acc[mi][ni][half * 2 + 0] + bias[c];
                    float v1 = acc[mi][ni][half * 2 + 1] + bias[c + 1];
                    v0 = v0 / (1.f + __expf(-v0));
                    v1 = v1 / (1.f + __expf(-v1));
                    *(__half2*)(g_Hh + rowbase + c) = __floats2half2_rn(v0, v1);
                }
            } else {
                int tok = g_tok[e * CAP + m];
                float w = g_wtl[e * CAP + m];
                float* orow = outp + (size_t)tok * NDIM;
#pragma unroll
                for (int ni = 0; ni < 4; ni++) {
                    int c = n0 + wn * 32 + ni * 8 + tig * 2;
                    // exactly 2 contributions per element, fp32 add commutative
                    atomicAdd(&orow[c],     (acc[mi][ni][half * 2 + 0] + bias[c]) * w);
                    atomicAdd(&orow[c + 1], (acc[mi][ni][half * 2 + 1] + bias[c + 1]) * w);
                }
            }
        }
    }
}

// ---------------- host: TMA descriptor builder --------------------------------
typedef CUresult (*PFN_encode)(CUtensorMap*, CUtensorMapDataType, cuuint32_t, void*,
    const cuuint64_t*, const cuuint64_t*, const cuuint32_t*, const cuuint32_t*,
    CUtensorMapInterleave, CUtensorMapSwizzle, CUtensorMapL2promotion,
    CUtensorMapFloatOOBfill);

static void make_map(PFN_encode enc, CUtensorMap* m, void* base,
                     uint64_t d0, uint64_t d1, uint32_t box1) {
    cuuint64_t dims[2] = {d0, d1};
    cuuint64_t strides[1] = {d0 * 2};           // bytes between rows
    cuuint32_t box[2] = {64, box1};             // 64 uint16 = 128B = SW128 atom
    cuuint32_t es[2] = {1, 1};
    enc(m, CU_TENSOR_MAP_DATA_TYPE_UINT16, 2, base, dims, strides, box, es,
        CU_TENSOR_MAP_INTERLEAVE_NONE, CU_TENSOR_MAP_SWIZZLE_128B,
        CU_TENSOR_MAP_L2_PROMOTION_L2_128B, CU_TENSOR_MAP_FLOAT_OOB_FILL_NONE);
}

// ---------------- launch ------------------------------------------------------
extern "C" void kernel_launch(void* const* d_in, const int* in_sizes, int n_in,
                              void* d_out, int out_size) {
    const float* x  = (const float*)d_in[0];
    const float* gw = (const float*)d_in[1];
    const float* W1 = (const float*)d_in[2];
    const float* b1 = (const float*)d_in[3];
    const float* W2 = (const float*)d_in[4];
    const float* b2 = (const float*)d_in[5];
    float* out = (float*)d_out;

    // TMA descriptors: driver entry point via runtime (no -lcuda), on stable
    // device-symbol addresses -> deterministic, graph-capture-safe.
    void* fn = nullptr;
    cudaDriverEntryPointQueryResult qr;
    cudaGetDriverEntryPoint("cuTensorMapEncodeTiled", &fn, cudaEnableDefault, &qr);
    PFN_encode enc = (PFN_encode)fn;
    void *pX, *pH, *pW1, *pW2;
    cudaGetSymbolAddress(&pX,  g_Xh);
    cudaGetSymbolAddress(&pH,  g_Hh);
    cudaGetSymbolAddress(&pW1, g_W1h);
    cudaGetSymbolAddress(&pW2, g_W2h);
    CUtensorMap mA1, mB1, mA2, mB2;
    make_map(enc, &mA1, pX,  DIM, (uint64_t)(RTOT + PADR), 128);
    make_map(enc, &mB1, pW1, DIM, (uint64_t)NEXP * DFF,    256);
    make_map(enc, &mA2, pH,  DFF, (uint64_t)(RTOT + PADR), 128);
    make_map(enc, &mB2, pW2, DFF, (uint64_t)NEXP * DIM,    256);

    // opt into >48KB dynamic smem (attribute call, not an allocation)
    constexpr int GEMM_SMEM = 2048 + 4 * 49152;   // 198,656 B
    cudaFuncSetAttribute(ffn_gemm<DIM, DFF, 0>,
                         cudaFuncAttributeMaxDynamicSharedMemorySize, GEMM_SMEM);
    cudaFuncSetAttribute(ffn_gemm<DFF, DIM, 1>,
                         cudaFuncAttributeMaxDynamicSharedMemorySize, GEMM_SMEM);

    zero_kernel<<<1, 32>>>();
    zero_out_kernel<<<(NTOK * (DIM / 4)) / 256, 256>>>((float4*)out);
    route_kernel<<<NTOK / 8, 256>>>(x, gw);
    prefix_kernel<<<1, 32>>>();

    // weight prep: fp16 convert + transpose to [N][K]
    wprep_kernel<0><<<dim3(DFF / 32, DIM / 32, NEXP), dim3(32, 8)>>>(W1);
    wprep_kernel<1><<<dim3(DIM / 32, DFF / 32, NEXP), dim3(32, 8)>>>(W2);
    gather_kernel<<<dim3(CAP, NEXP), 128>>>(x);

    // GEMM1: (CAP/128) * (DFF/256) = 128 * 16 blocks, z = experts
    ffn_gemm<DIM, DFF, 0><<<dim3((CAP / 128) * (DFF / 256), 1, NEXP), 512, GEMM_SMEM>>>(
        b1, nullptr, mA1, mB1);
    // GEMM2: accumulates straight into out (two slots per token, commutative)
    ffn_gemm<DFF, DIM, 1><<<dim3((CAP / 128) * (DIM / 256), 1, NEXP), 512, GEMM_SMEM>>>(
        b2, out, mA2, mB2);
}

// round 17
// speedup vs baseline: 1.2825x; 1.0252x over previous
#include <cuda_runtime.h>
#include <cuda.h>
#include <cuda_fp16.h>
#include <cstdint>
#include <cstddef>

// Problem constants
#define NEXP 8
#define TOPK 2
#define DIM 1024
#define DFF 4096
#define NTOK 16384          // B*S
#define CAP  16384          // per-expert capacity
#define RTOT (NTOK * TOPK)  // 32768 expert-rows
#define PADR 128            // row padding for tile overrun

// ---------------- scratch (device globals; DEVICE-CODE REFERENCES ONLY) ------
// RULE (rounds 2-5): never pass these symbols as host-side kernel args — the
// host shadow is ATS-readable on GB300 and silently reads zeros. (Taking their
// device address via cudaGetSymbolAddress for TMA descriptors is fine.)
__device__ int    g_cnt[NEXP];
__device__ int    g_off[NEXP];
__device__ int    g_tok[NEXP * CAP];
__device__ float  g_wtl[NEXP * CAP];
__device__ __half g_Xh[(size_t)(RTOT + PADR) * DIM];   // gathered x, fp16
__device__ __half g_Hh[(size_t)(RTOT + PADR) * DFF];   // hidden scratch, fp16
__device__ __half g_W1h[(size_t)NEXP * DIM * DFF];     // W1^T: [DFF][DIM], fp16
__device__ __half g_W2h[(size_t)NEXP * DFF * DIM];     // W2^T: [DIM][DFF], fp16

// ---------------- helpers ----------------------------------------------------
__device__ __forceinline__ void mma_f16(float c[4], const unsigned a[4], const unsigned b[2]) {
    asm volatile(
        "mma.sync.aligned.m16n8k16.row.col.f32.f16.f16.f32 "
        "{%0,%1,%2,%3}, {%4,%5,%6,%7}, {%8,%9}, {%0,%1,%2,%3};\n"
        : "+f"(c[0]), "+f"(c[1]), "+f"(c[2]), "+f"(c[3])
        : "r"(a[0]), "r"(a[1]), "r"(a[2]), "r"(a[3]), "r"(b[0]), "r"(b[1]));
}
__device__ __forceinline__ void ldsm_x4(unsigned& r0, unsigned& r1, unsigned& r2,
                                        unsigned& r3, uint32_t addr) {
    asm volatile("ldmatrix.sync.aligned.m8n8.x4.shared.b16 {%0,%1,%2,%3}, [%4];"
                 : "=r"(r0), "=r"(r1), "=r"(r2), "=r"(r3) : "r"(addr));
}
__device__ __forceinline__ void mbar_init(uint32_t a, uint32_t cnt) {
    asm volatile("mbarrier.init.shared.b64 [%0], %1;" :: "r"(a), "r"(cnt) : "memory");
}
__device__ __forceinline__ void mbar_expect_tx(uint32_t a, uint32_t bytes) {
    asm volatile("mbarrier.arrive.expect_tx.shared.b64 _, [%0], %1;"
                 :: "r"(a), "r"(bytes) : "memory");
}
__device__ __forceinline__ void mbar_wait(uint32_t a, uint32_t parity) {
    asm volatile(
        "{\n\t.reg .pred P;\n"
        "LW_%=:\n\t"
        "mbarrier.try_wait.parity.acquire.cta.shared::cta.b64 P, [%0], %1;\n\t"
        "@!P bra LW_%=;\n\t}"
        :: "r"(a), "r"(parity) : "memory");
}
__device__ __forceinline__ void tma_ld_2d(uint32_t dst, const void* map,
                                          int c0, int c1, uint32_t mbar) {
    asm volatile(
        "cp.async.bulk.tensor.2d.shared::cta.global.tile.mbarrier::complete_tx::bytes "
        "[%0], [%1, {%2, %3}], [%4];"
        :: "r"(dst), "l"(map), "r"(c0), "r"(c1), "r"(mbar) : "memory");
}

// ---------------- kernel 0: zero out + counters (fused) -----------------------
__global__ void zero_out_kernel(float4* __restrict__ out) {
    if (blockIdx.x == 0 && threadIdx.x < NEXP) g_cnt[threadIdx.x] = 0;
    out[blockIdx.x * 256 + threadIdx.x] = make_float4(0.f, 0.f, 0.f, 0.f);
}

// ---------------- kernel 1: routing (one warp per token) ----------------------
__global__ void route_kernel(const float* __restrict__ x, const float* __restrict__ gw) {
    __shared__ float s_gw[NEXP * DIM];
    int tid = threadIdx.x;
    for (int i = tid; i < NEXP * DIM; i += blockDim.x) s_gw[i] = gw[i];
    __syncthreads();

    int warp = tid >> 5, lane = tid & 31;
    int t = blockIdx.x * (blockDim.x >> 5) + warp;
    if (t >= NTOK) return;

    const float* xr = x + (size_t)t * DIM;
    float xv[32];
#pragma unroll
    for (int i = 0; i < 32; i++) xv[i] = xr[i * 32 + lane];

    float logit[NEXP];
#pragma unroll
    for (int e = 0; e < NEXP; e++) {
        float acc = 0.f;
#pragma unroll
        for (int i = 0; i < 32; i++) acc += xv[i] * s_gw[e * DIM + i * 32 + lane];
#pragma unroll
        for (int o = 16; o; o >>= 1) acc += __shfl_xor_sync(0xffffffffu, acc, o);
        logit[e] = acc;
    }

    if (lane == 0) {
        int i0 = 0;
#pragma unroll
        for (int e = 1; e < NEXP; e++) if (logit[e] > logit[i0]) i0 = e;
        int i1 = (i0 == 0) ? 1 : 0;
#pragma unroll
        for (int e = 0; e < NEXP; e++) {
            if (e == i0 || e == i1) continue;
            if (logit[e] > logit[i1]) i1 = e;
        }
        float ee = __expf(logit[i1] - logit[i0]);
        float inv = 1.f / (1.f + ee);
        int p0 = atomicAdd(&g_cnt[i0], 1);
        g_tok[i0 * CAP + p0] = t;  g_wtl[i0 * CAP + p0] = inv;
        int p1 = atomicAdd(&g_cnt[i1], 1);
        g_tok[i1 * CAP + p1] = t;  g_wtl[i1 * CAP + p1] = ee * inv;
    }
}

// ---------------- kernel 2: weight prep (+ fused prefix on WHICH==0) ----------
template <int WHICH>   // 0: W1 (K=DIM, N=DFF) -> g_W1h;  1: W2 (K=DFF, N=DIM) -> g_W2h
__global__ void wprep_kernel(const float* __restrict__ src) {
    constexpr int K = WHICH ? DFF : DIM;
    constexpr int N = WHICH ? DIM : DFF;
    __shared__ float t[32][33];

    // fused prefix: runs after route (serial stream), before gather
    if (WHICH == 0 && blockIdx.x == 0 && blockIdx.y == 0 && blockIdx.z == 0 &&
        threadIdx.x == 0 && threadIdx.y == 0) {
        int s = 0;
#pragma unroll
        for (int e = 0; e < NEXP; e++) { g_off[e] = s; s += g_cnt[e]; }
    }

    __half* dall = WHICH ? g_W2h : g_W1h;          // device-side symbol
    int e = blockIdx.z;
    const float* s = src + (size_t)e * K * N;
    __half* d = dall + (size_t)e * K * N;
    int nb = blockIdx.x * 32, kb = blockIdx.y * 32;
    int tx = threadIdx.x, ty = threadIdx.y;        // block (32, 8)
#pragma unroll
    for (int j = 0; j < 4; j++)
        t[ty + j * 8][tx] = s[(size_t)(kb + ty + j * 8) * N + nb + tx];
    __syncthreads();
#pragma unroll
    for (int j = 0; j < 4; j++)
        d[(size_t)(nb + ty + j * 8) * K + kb + tx] = __float2half_rn(t[tx][ty + j * 8]);
}

// ---------------- kernel 3: gather x -> fp16 (flat grid, no empty blocks) -----
__global__ void gather_kernel(const float* __restrict__ x) {
    int row = blockIdx.x;                          // 0 .. RTOT-1 (all valid)
    int e = 0;
#pragma unroll
    for (int i = 1; i < NEXP; i++) if (row >= g_off[i]) e = i;   // ascending
    int m = row - g_off[e];
    int tok = g_tok[e * CAP + m];
    const float4* src = (const float4*)(x + (size_t)tok * DIM);
    int t = threadIdx.x;                           // 128 threads, 8 halves each
    float4 a = src[2 * t], b = src[2 * t + 1];
    union { uint4 u; __half2 h[4]; } pk;
    pk.h[0] = __floats2half2_rn(a.x, a.y);
    pk.h[1] = __floats2half2_rn(a.z, a.w);
    pk.h[2] = __floats2half2_rn(b.x, b.y);
    pk.h[3] = __floats2half2_rn(b.z, b.w);
    *(uint4*)(g_Xh + (size_t)row * DIM + t * 8) = pk.u;
}

// ---------------- kernels 4/5: TMA + ldmatrix fp16 grouped GEMM ---------------
// 512 threads: 16 warps, 2(M) x 8(N), warp tile 64x32. CTA tile 128x256x64.
// Tiles land via cp.async.bulk.tensor.2d (SW128, 128B rows = BK*2) into a
// 4-stage ring; one mbarrier (count=1, expect_tx=49152B) per stage; the single
// __syncthreads per kt retires stage reads before reissue (R15 protocol).
// ldmatrix addresses apply the SW128 XOR: chunk ^= (row & 7).
// MODE 0: Hh = fp16(silu(Xh @ W1 + b1))   (KDIM=DIM,  NDIM=DFF)
// MODE 1: out[tok] += (Hh @ W2 + b2) * wt (KDIM=DFF,  NDIM=DIM)  [atomicAdd]
template <int KDIM, int NDIM, int MODE>
__global__ void __launch_bounds__(512, 1) ffn_gemm(const float* __restrict__ ball,
                                                   float* __restrict__ outp,
                                                   const __grid_constant__ CUtensorMap mapA,
                                                   const __grid_constant__ CUtensorMap mapB) {
    constexpr int BM = 128, BN = 256, BK = 64, STAGES = 4;
    constexpr int ABYTES = BM * 128;            // 16384 (128B rows, SW128)
    constexpr int BBYTES = BN * 128;            // 32768
    constexpr int STGB = ABYTES + BBYTES;       // 49152 per stage
    constexpr int KT = KDIM / BK;
    constexpr int NN = NDIM / BN;
    constexpr int GM = 16;                      // raster group (L2 reuse)

    extern __shared__ __align__(16) char smraw[];
    uint32_t sbase = (uint32_t)__cvta_generic_to_shared(smraw);
    uint32_t mb = sbase;                                    // 4 mbarriers (8B each)
    uint32_t ab = (sbase + 32 + 1023) & ~1023u;             // 1024-aligned stages

    int e = blockIdx.z;
    int cnt = g_cnt[e];
    int per = GM * NN;
    int grp = blockIdx.x / per;
    int rem = blockIdx.x - grp * per;
    int mbk = grp * GM + (rem % GM);
    int nb = rem / GM;
    int m0 = mbk * BM;
    if (m0 >= cnt) return;
    int n0 = nb * BN;
    int off = g_off[e];

    const float* bias = ball + (size_t)e * NDIM;
    int arow0 = off + m0;                       // A row coord (gathered rows)
    int brow0 = e * NDIM + n0;                  // W^T row coord

    int tid = threadIdx.x;
    int warp = tid >> 5, lane = tid & 31;
    int wm = warp & 1, wn = warp >> 1;          // 2 (M) x 8 (N); warp tile 64x32
    int group = lane >> 2, tig = lane & 3;
    int lrow = lane & 15, lhi = lane >> 4;      // ldmatrix row / k-half select

    if (tid == 0) {
#pragma unroll
        for (int s = 0; s < STAGES; s++) mbar_init(mb + 8 * s, 1);
    }
    __syncthreads();                            // init visible before any wait

    auto issue = [&](int kt) {
        int st = kt & 3;
        uint32_t base = ab + (uint32_t)st * STGB;
        mbar_expect_tx(mb + 8 * st, STGB);
        tma_ld_2d(base,          &mapA, kt * BK, arow0, mb + 8 * st);
        tma_ld_2d(base + ABYTES, &mapB, kt * BK, brow0, mb + 8 * st);
    };

    if (tid == 0) { issue(0); issue(1); issue(2); }

    float acc[4][4][4];
#pragma unroll
    for (int mi = 0; mi < 4; mi++)
#pragma unroll
        for (int ni = 0; ni < 4; ni++)
#pragma unroll
            for (int r = 0; r < 4; r++) acc[mi][ni][r] = 0.f;

    for (int kt = 0; kt < KT; kt++) {
        int st = kt & 3;
        mbar_wait(mb + 8 * st, (kt >> 2) & 1);  // stage kt data arrived
        __syncthreads();                        // all warps past wait; reads of
                                                // stage kt-1 retired (R15 proof)
        if (tid == 0 && kt + 3 < KT) issue(kt + 3);   // reuses stage (kt-1)&3

        uint32_t sA = ab + (uint32_t)st * STGB;
        uint32_t sB = sA + ABYTES;
#pragma unroll
        for (int ks = 0; ks < 4; ks++) {        // K=16 per step
            int c = ks * 2 + lhi;               // 16B chunk index (0..7)
            unsigned af[4][4], bf[4][2];
#pragma unroll
            for (int mi = 0; mi < 4; mi++) {
                int r = wm * 64 + mi * 16 + lrow;
                uint32_t addr = sA + (uint32_t)(r * 128 + ((c ^ (r & 7)) << 4));
                ldsm_x4(af[mi][0], af[mi][1], af[mi][2], af[mi][3], addr);
            }
#pragma unroll
            for (int nj = 0; nj < 2; nj++) {
                int r = wn * 32 + nj * 16 + lrow;
                uint32_t addr = sB + (uint32_t)(r * 128 + ((c ^ (r & 7)) << 4));
                unsigned r0, r1, r2, r3;
                ldsm_x4(r0, r1, r2, r3, addr);
                bf[2 * nj][0]     = r0;  bf[2 * nj][1]     = r2;   // n 0-7
                bf[2 * nj + 1][0] = r1;  bf[2 * nj + 1][1] = r3;   // n 8-15
            }
#pragma unroll
            for (int mi = 0; mi < 4; mi++)
#pragma unroll
                for (int ni = 0; ni < 4; ni++)
                    mma_f16(acc[mi][ni], af[mi], bf[ni]);
        }
    }

    // epilogue (fp32 math; MODE 0 -> fp16 H, MODE 1 -> atomicAdd to out)
#pragma unroll
    for (int mi = 0; mi < 4; mi++) {
#pragma unroll
        for (int half = 0; half < 2; half++) {
            int m = m0 + wm * 64 + mi * 16 + group + half * 8;
            if (m >= cnt) continue;
            if (MODE == 0) {
                size_t rowbase = (size_t)(off + m) * NDIM;
#pragma unroll
                for (int ni = 0; ni < 4; ni++) {
                    int c = n0 + wn * 32 + ni * 8 + tig * 2;
                    float v0 = acc[mi][ni][half * 2 + 0] + bias[c];
                    float v1 = acc[mi][ni][half * 2 + 1] + bias[c + 1];
                    v0 = v0 / (1.f + __expf(-v0));
                    v1 = v1 / (1.f + __expf(-v1));
                    *(__half2*)(g_Hh + rowbase + c) = __floats2half2_rn(v0, v1);
                }
            } else {
                int tok = g_tok[e * CAP + m];
                float w = g_wtl[e * CAP + m];
                float* orow = outp + (size_t)tok * NDIM;
#pragma unroll
                for (int ni = 0; ni < 4; ni++) {
                    int c = n0 + wn * 32 + ni * 8 + tig * 2;
                    // exactly 2 contributions per element, fp32 add commutative
                    atomicAdd(&orow[c],     (acc[mi][ni][half * 2 + 0] + bias[c]) * w);
                    atomicAdd(&orow[c + 1], (acc[mi][ni][half * 2 + 1] + bias[c + 1]) * w);
                }
            }
        }
    }
}

// ---------------- host: TMA descriptor builder --------------------------------
typedef CUresult (*PFN_encode)(CUtensorMap*, CUtensorMapDataType, cuuint32_t, void*,
    const cuuint64_t*, const cuuint64_t*, const cuuint32_t*, const cuuint32_t*,
    CUtensorMapInterleave, CUtensorMapSwizzle, CUtensorMapL2promotion,
    CUtensorMapFloatOOBfill);

static void make_map(PFN_encode enc, CUtensorMap* m, void* base,
                     uint64_t d0, uint64_t d1, uint32_t box1) {
    cuuint64_t dims[2] = {d0, d1};
    cuuint64_t strides[1] = {d0 * 2};           // bytes between rows
    cuuint32_t box[2] = {64, box1};             // 64 uint16 = 128B = SW128 atom
    cuuint32_t es[2] = {1, 1};
    enc(m, CU_TENSOR_MAP_DATA_TYPE_UINT16, 2, base, dims, strides, box, es,
        CU_TENSOR_MAP_INTERLEAVE_NONE, CU_TENSOR_MAP_SWIZZLE_128B,
        CU_TENSOR_MAP_L2_PROMOTION_L2_128B, CU_TENSOR_MAP_FLOAT_OOB_FILL_NONE);
}

// ---------------- launch ------------------------------------------------------
extern "C" void kernel_launch(void* const* d_in, const int* in_sizes, int n_in,
                              void* d_out, int out_size) {
    const float* x  = (const float*)d_in[0];
    const float* gw = (const float*)d_in[1];
    const float* W1 = (const float*)d_in[2];
    const float* b1 = (const float*)d_in[3];
    const float* W2 = (const float*)d_in[4];
    const float* b2 = (const float*)d_in[5];
    float* out = (float*)d_out;

    // TMA descriptors: driver entry point via runtime (no -lcuda), on stable
    // device-symbol addresses -> deterministic, graph-capture-safe.
    void* fn = nullptr;
    cudaDriverEntryPointQueryResult qr;
    cudaGetDriverEntryPoint("cuTensorMapEncodeTiled", &fn, cudaEnableDefault, &qr);
    PFN_encode enc = (PFN_encode)fn;
    void *pX, *pH, *pW1, *pW2;
    cudaGetSymbolAddress(&pX,  g_Xh);
    cudaGetSymbolAddress(&pH,  g_Hh);
    cudaGetSymbolAddress(&pW1, g_W1h);
    cudaGetSymbolAddress(&pW2, g_W2h);
    CUtensorMap mA1, mB1, mA2, mB2;
    make_map(enc, &mA1, pX,  DIM, (uint64_t)(RTOT + PADR), 128);
    make_map(enc, &mB1, pW1, DIM, (uint64_t)NEXP * DFF,    256);
    make_map(enc, &mA2, pH,  DFF, (uint64_t)(RTOT + PADR), 128);
    make_map(enc, &mB2, pW2, DFF, (uint64_t)NEXP * DIM,    256);

    // opt into >48KB dynamic smem (attribute call, not an allocation)
    constexpr int GEMM_SMEM = 2048 + 4 * 49152;   // 198,656 B
    cudaFuncSetAttribute(ffn_gemm<DIM, DFF, 0>,
                         cudaFuncAttributeMaxDynamicSharedMemorySize, GEMM_SMEM);
    cudaFuncSetAttribute(ffn_gemm<DFF, DIM, 1>,
                         cudaFuncAttributeMaxDynamicSharedMemorySize, GEMM_SMEM);

    // fused pipeline: zero(out+cnt) -> route -> wprep0(+prefix) -> wprep1
    //                 -> gather -> gemm1 -> gemm2
    zero_out_kernel<<<(NTOK * (DIM / 4)) / 256, 256>>>((float4*)out);
    route_kernel<<<NTOK / 8, 256>>>(x, gw);
    wprep_kernel<0><<<dim3(DFF / 32, DIM / 32, NEXP), dim3(32, 8)>>>(W1);
    wprep_kernel<1><<<dim3(DIM / 32, DFF / 32, NEXP), dim3(32, 8)>>>(W2);
    gather_kernel<<<RTOT, 128>>>(x);

    // GEMM1: (CAP/128) * (DFF/256) = 128 * 16 blocks, z = experts
    ffn_gemm<DIM, DFF, 0><<<dim3((CAP / 128) * (DFF / 256), 1, NEXP), 512, GEMM_SMEM>>>(
        b1, nullptr, mA1, mB1);
    // GEMM2: accumulates straight into out (two slots per token, commutative)
    ffn_gemm<DFF, DIM, 1><<<dim3((CAP / 128) * (DIM / 256), 1, NEXP), 512, GEMM_SMEM>>>(
        b2, out, mA2, mB2);
}